// round 1
// baseline (speedup 1.0000x reference)
#include <cuda_runtime.h>
#include <cstdint>

#define N_INST 64
#define HW 64000   // 200*320
#define MASK_ELEMS (N_INST * HW)

// O matrix scratch (no cudaMalloc allowed)
__device__ float g_O[N_INST * N_INST];

__device__ __forceinline__ float sigmoidf_(float x) {
    return __fdividef(1.0f, 1.0f + __expf(-x));
}

__device__ __forceinline__ unsigned long long pack2_(float lo, float hi) {
    unsigned long long d;
    asm("mov.b64 %0, {%1, %2};" : "=l"(d) : "f"(lo), "f"(hi));
    return d;
}

__device__ __forceinline__ void unpack2_(unsigned long long v, float& lo, float& hi) {
    asm("mov.b64 {%0, %1}, %2;" : "=f"(lo), "=f"(hi) : "l"(v));
}

// Packed 2xfp32 FMA (SASS FFMA2) — only reachable via PTX fma.rn.f32x2
__device__ __forceinline__ unsigned long long fma2_(unsigned long long a,
                                                    unsigned long long b,
                                                    unsigned long long c) {
    unsigned long long d;
    asm("fma.rn.f32x2 %0, %1, %2, %3;" : "=l"(d) : "l"(a), "l"(b), "l"(c));
    return d;
}

// ---------------------------------------------------------------------------
// Kernel 1: one warp per (i,j) pair. Computes BOTH logit(i,j) and logit(j,i),
// then O[i,j] = relu(sigmoid(l_ij) - sigmoid(l_ji)) directly (no R pass).
// ---------------------------------------------------------------------------
__global__ void relation_O_kernel(const float* __restrict__ bbox,
                                  const int*   __restrict__ cls_idx,
                                  const float* __restrict__ U_w,   // (256,80)
                                  const float* __restrict__ V_w,   // (256,80)
                                  const float* __restrict__ Wc_w,  // (128,4)
                                  const float* __restrict__ P_w,   // (384,)
                                  float* __restrict__ out_O)
{
    int warp = (blockIdx.x * blockDim.x + threadIdx.x) >> 5;
    int lane = threadIdx.x & 31;
    if (warp >= N_INST * N_INST) return;
    int i = warp >> 6;
    int j = warp & 63;

    int ki = cls_idx[i] - 1;
    int kj = cls_idx[j] - 1;

    float s_ij = 0.f, s_ji = 0.f;

    // cls_rel term: sum_c relu(U[c,ki])*relu(V[c,kj])*P[c]  (and swapped)
    #pragma unroll
    for (int c = lane; c < 256; c += 32) {
        float ui = fmaxf(U_w[c * 80 + ki], 0.f);
        float uj = fmaxf(U_w[c * 80 + kj], 0.f);
        float vi = fmaxf(V_w[c * 80 + ki], 0.f);
        float vj = fmaxf(V_w[c * 80 + kj], 0.f);
        float p  = P_w[c];
        s_ij += ui * vj * p;
        s_ji += uj * vi * p;
    }

    // position matrix terms
    float x0i = bbox[i * 5 + 1], y0i = bbox[i * 5 + 2];
    float x1i = bbox[i * 5 + 3], y1i = bbox[i * 5 + 4];
    float x0j = bbox[j * 5 + 1], y0j = bbox[j * 5 + 2];
    float x1j = bbox[j * 5 + 3], y1j = bbox[j * 5 + 4];
    float wi = x1i - x0i + 1.f, hi = y1i - y0i + 1.f;
    float wj = x1j - x0j + 1.f, hj = y1j - y0j + 1.f;
    float xci = x0i + 0.5f * wi, yci = y0i + 0.5f * hi;
    float xcj = x0j + 0.5f * wj, ycj = y0j + 0.5f * hj;

    float dx_ij = -(xci - xcj) / wi, dy_ij = -(yci - ycj) / hi;
    float dw_ij = __logf(wj / wi),   dh_ij = __logf(hj / hi);
    float dx_ji = -(xcj - xci) / wj, dy_ji = -(ycj - yci) / hj;
    float dw_ji = __logf(wi / wj),   dh_ji = __logf(hi / hj);

    #pragma unroll
    for (int o = lane; o < 128; o += 32) {
        float4 w4 = *reinterpret_cast<const float4*>(&Wc_w[o * 4]);
        float p = P_w[256 + o];
        float a = dx_ij * w4.x + dy_ij * w4.y + dw_ij * w4.z + dh_ij * w4.w;
        float b = dx_ji * w4.x + dy_ji * w4.y + dw_ji * w4.z + dh_ji * w4.w;
        s_ij += fmaxf(a, 0.f) * p;
        s_ji += fmaxf(b, 0.f) * p;
    }

    #pragma unroll
    for (int off = 16; off; off >>= 1) {
        s_ij += __shfl_xor_sync(0xffffffffu, s_ij, off);
        s_ji += __shfl_xor_sync(0xffffffffu, s_ji, off);
    }

    if (lane == 0) {
        float r_ij = sigmoidf_(s_ij);
        float r_ji = sigmoidf_(s_ji);
        float o = fmaxf(r_ij - r_ji, 0.f);
        g_O[i * 64 + j]   = o;
        out_O[i * 64 + j] = o;
    }
}

// ---------------------------------------------------------------------------
// Kernel 2: mask update. Each thread owns 2 adjacent pixels (packed f32x2),
// keeps 64 packed accumulators in registers, streams j with O pre-duplicated
// (o,o) in shared memory so FFMA2 gets its splat operand via broadcast LDS.
// ---------------------------------------------------------------------------
__global__ void __launch_bounds__(256)
mask_update_kernel(const float* __restrict__ mask, float* __restrict__ out)
{
    __shared__ unsigned long long Osh[64 * 64];  // [j][i], duplicated (o,o)

    int tid = threadIdx.x;
    #pragma unroll
    for (int k = tid; k < 4096; k += 256) {
        int i = k >> 6, j = k & 63;
        float o = g_O[k];
        Osh[j * 64 + i] = pack2_(o, o);
    }
    __syncthreads();

    int p = (blockIdx.x * 256 + tid) * 2;

    unsigned long long acc[64];
    #pragma unroll
    for (int i = 0; i < 64; i++) acc[i] = 0ull;

    for (int j = 0; j < 64; j++) {
        float2 mm = *reinterpret_cast<const float2*>(mask + (size_t)j * HW + p);
        unsigned long long t2 = pack2_(sigmoidf_(mm.x), sigmoidf_(mm.y));
        const ulonglong2* orow = reinterpret_cast<const ulonglong2*>(&Osh[j * 64]);
        #pragma unroll
        for (int g = 0; g < 32; g++) {
            ulonglong2 o2 = orow[g];
            acc[2 * g + 0] = fma2_(o2.x, t2, acc[2 * g + 0]);
            acc[2 * g + 1] = fma2_(o2.y, t2, acc[2 * g + 1]);
        }
    }

    #pragma unroll
    for (int i = 0; i < 64; i++) {
        float2 mm = *reinterpret_cast<const float2*>(mask + (size_t)i * HW + p);
        float tx = sigmoidf_(mm.x);
        float ty = sigmoidf_(mm.y);
        float wx, wy;
        unpack2_(acc[i], wx, wy);
        float2 r;
        r.x = mm.x - mm.x * tx * wx;
        r.y = mm.y - mm.y * ty * wy;
        *reinterpret_cast<float2*>(out + (size_t)i * HW + p) = r;
    }
}

extern "C" void kernel_launch(void* const* d_in, const int* in_sizes, int n_in,
                              void* d_out, int out_size)
{
    const float* mask    = (const float*)d_in[0];
    const float* bbox    = (const float*)d_in[1];
    const int*   cls_idx = (const int*)  d_in[2];
    const float* U_w     = (const float*)d_in[3];
    const float* V_w     = (const float*)d_in[4];
    const float* Wc_w    = (const float*)d_in[5];
    const float* P_w     = (const float*)d_in[6];

    float* out_mask = (float*)d_out;                 // 4,096,000 elems
    float* out_O    = (float*)d_out + MASK_ELEMS;    // 4,096 elems

    // 4096 warps, one per (i,j)
    relation_O_kernel<<<512, 256>>>(bbox, cls_idx, U_w, V_w, Wc_w, P_w, out_O);

    // 64000 pixels / 2 per thread = 32000 threads = 125 blocks x 256
    mask_update_kernel<<<125, 256>>>(mask, out_mask);
}

// round 3
// speedup vs baseline: 1.3734x; 1.3734x over previous
#include <cuda_runtime.h>
#include <cstdint>

#define N_INST 64
#define HW 64000   // 200*320
#define MASK_ELEMS (N_INST * HW)

// Scratch (no cudaMalloc allowed):
// g_Odup[j*64+i] = (O[i][j], O[i][j]) packed as 2xf32 in 64 bits (transposed + duplicated)
__device__ unsigned long long g_Odup[N_INST * N_INST];

__device__ __forceinline__ float sigmoidf_(float x) {
    return __fdividef(1.0f, 1.0f + __expf(-x));
}

__device__ __forceinline__ unsigned long long pack2_(float lo, float hi) {
    unsigned long long d;
    asm("mov.b64 %0, {%1, %2};" : "=l"(d) : "f"(lo), "f"(hi));
    return d;
}

__device__ __forceinline__ void unpack2_(unsigned long long v, float& lo, float& hi) {
    asm("mov.b64 {%0, %1}, %2;" : "=f"(lo), "=f"(hi) : "l"(v));
}

// Packed 2xfp32 FMA (SASS FFMA2) — only reachable via PTX fma.rn.f32x2
__device__ __forceinline__ unsigned long long fma2_(unsigned long long a,
                                                    unsigned long long b,
                                                    unsigned long long c) {
    unsigned long long d;
    asm("fma.rn.f32x2 %0, %1, %2, %3;" : "=l"(d) : "l"(a), "l"(b), "l"(c));
    return d;
}

// ---------------------------------------------------------------------------
// Kernel 1: one warp per unordered pair (i<j). Both logits computed once;
// exactly one of O[i,j]/O[j,i] is nonzero, both written. Separate warps
// zero the diagonal. Writes out_O and the transposed+duplicated g_Odup.
// ---------------------------------------------------------------------------
__global__ void relation_O_kernel(const float* __restrict__ bbox,
                                  const int*   __restrict__ cls_idx,
                                  const float* __restrict__ U_w,   // (256,80)
                                  const float* __restrict__ V_w,   // (256,80)
                                  const float* __restrict__ Wc_w,  // (128,4)
                                  const float* __restrict__ P_w,   // (384,)
                                  float* __restrict__ out_O)
{
    int warp = (blockIdx.x * blockDim.x + threadIdx.x) >> 5;
    int lane = threadIdx.x & 31;
    const int NPAIR = (N_INST * (N_INST - 1)) / 2;   // 2016
    if (warp >= NPAIR + N_INST) return;

    if (warp >= NPAIR) {                              // diagonal zeros
        if (lane == 0) {
            int i = warp - NPAIR;
            out_O[i * 64 + i]  = 0.f;
            g_Odup[i * 64 + i] = 0ull;
        }
        return;
    }

    // decode i < j from triangular index: warp = j*(j-1)/2 + i
    int j = (int)((1.0f + sqrtf(8.0f * (float)warp + 1.0f)) * 0.5f);
    while (j * (j - 1) / 2 > warp) j--;
    while ((j + 1) * j / 2 <= warp) j++;
    int i = warp - j * (j - 1) / 2;

    int ki = cls_idx[i] - 1;
    int kj = cls_idx[j] - 1;

    float s_ij = 0.f, s_ji = 0.f;

    #pragma unroll
    for (int c = lane; c < 256; c += 32) {
        float ui = fmaxf(U_w[c * 80 + ki], 0.f);
        float uj = fmaxf(U_w[c * 80 + kj], 0.f);
        float vi = fmaxf(V_w[c * 80 + ki], 0.f);
        float vj = fmaxf(V_w[c * 80 + kj], 0.f);
        float p  = P_w[c];
        s_ij += ui * vj * p;
        s_ji += uj * vi * p;
    }

    float x0i = bbox[i * 5 + 1], y0i = bbox[i * 5 + 2];
    float x1i = bbox[i * 5 + 3], y1i = bbox[i * 5 + 4];
    float x0j = bbox[j * 5 + 1], y0j = bbox[j * 5 + 2];
    float x1j = bbox[j * 5 + 3], y1j = bbox[j * 5 + 4];
    float wi = x1i - x0i + 1.f, hi = y1i - y0i + 1.f;
    float wj = x1j - x0j + 1.f, hj = y1j - y0j + 1.f;
    float xci = x0i + 0.5f * wi, yci = y0i + 0.5f * hi;
    float xcj = x0j + 0.5f * wj, ycj = y0j + 0.5f * hj;

    float dx_ij = -(xci - xcj) / wi, dy_ij = -(yci - ycj) / hi;
    float dw_ij = __logf(wj / wi),   dh_ij = __logf(hj / hi);
    float dx_ji = -(xcj - xci) / wj, dy_ji = -(ycj - yci) / hj;
    float dw_ji = __logf(wi / wj),   dh_ji = __logf(hi / hj);

    #pragma unroll
    for (int o = lane; o < 128; o += 32) {
        float4 w4 = *reinterpret_cast<const float4*>(&Wc_w[o * 4]);
        float p = P_w[256 + o];
        float a = dx_ij * w4.x + dy_ij * w4.y + dw_ij * w4.z + dh_ij * w4.w;
        float b = dx_ji * w4.x + dy_ji * w4.y + dw_ji * w4.z + dh_ji * w4.w;
        s_ij += fmaxf(a, 0.f) * p;
        s_ji += fmaxf(b, 0.f) * p;
    }

    #pragma unroll
    for (int off = 16; off; off >>= 1) {
        s_ij += __shfl_xor_sync(0xffffffffu, s_ij, off);
        s_ji += __shfl_xor_sync(0xffffffffu, s_ji, off);
    }

    if (lane == 0) {
        float r_ij = sigmoidf_(s_ij);
        float r_ji = sigmoidf_(s_ji);
        float o_ij = fmaxf(r_ij - r_ji, 0.f);
        float o_ji = fmaxf(r_ji - r_ij, 0.f);
        out_O[i * 64 + j]  = o_ij;
        out_O[j * 64 + i]  = o_ji;
        g_Odup[j * 64 + i] = pack2_(o_ij, o_ij);   // [col j][row i]
        g_Odup[i * 64 + j] = pack2_(o_ji, o_ji);
    }
}

// ---------------------------------------------------------------------------
// Kernel 2: mask update. blockIdx.y selects which half of the i-range (32
// output rows) this block owns -> 32 packed accumulators, ~110 regs,
// 2 CTAs/SM (16 warps). Each thread owns 2 adjacent pixels (packed f32x2).
// mask[j+1] is prefetched so the LDG latency overlaps the FMA stream.
// ---------------------------------------------------------------------------
__global__ void __launch_bounds__(256, 2)
mask_update_kernel(const float* __restrict__ mask, float* __restrict__ out)
{
    __shared__ unsigned long long Osh[64 * 32];  // [j][i_local], (o,o) pairs

    int tid = threadIdx.x;
    int ibase = blockIdx.y * 32;

    // coalesced copy of this i-half's O columns (already transposed+dup'd)
    #pragma unroll
    for (int k = tid; k < 2048; k += 256) {
        int j = k >> 5, il = k & 31;
        Osh[j * 32 + il] = g_Odup[j * 64 + (ibase + il)];
    }
    __syncthreads();

    int p = (blockIdx.x * 256 + tid) * 2;

    unsigned long long acc[32];
    #pragma unroll
    for (int i = 0; i < 32; i++) acc[i] = 0ull;

    float2 mm_next = *reinterpret_cast<const float2*>(mask + p);  // j = 0

    #pragma unroll 1
    for (int j = 0; j < 64; j++) {
        float2 mm = mm_next;
        if (j < 63)
            mm_next = *reinterpret_cast<const float2*>(mask + (size_t)(j + 1) * HW + p);
        unsigned long long t2 = pack2_(sigmoidf_(mm.x), sigmoidf_(mm.y));
        const ulonglong2* orow = reinterpret_cast<const ulonglong2*>(&Osh[j * 32]);
        #pragma unroll
        for (int g = 0; g < 16; g++) {
            ulonglong2 o2 = orow[g];
            acc[2 * g + 0] = fma2_(o2.x, t2, acc[2 * g + 0]);
            acc[2 * g + 1] = fma2_(o2.y, t2, acc[2 * g + 1]);
        }
    }

    #pragma unroll
    for (int il = 0; il < 32; il++) {
        int i = ibase + il;
        float2 mm = *reinterpret_cast<const float2*>(mask + (size_t)i * HW + p);
        float tx = sigmoidf_(mm.x);
        float ty = sigmoidf_(mm.y);
        float wx, wy;
        unpack2_(acc[il], wx, wy);
        float2 r;
        r.x = mm.x - mm.x * tx * wx;
        r.y = mm.y - mm.y * ty * wy;
        *reinterpret_cast<float2*>(out + (size_t)i * HW + p) = r;
    }
}

extern "C" void kernel_launch(void* const* d_in, const int* in_sizes, int n_in,
                              void* d_out, int out_size)
{
    const float* mask    = (const float*)d_in[0];
    const float* bbox    = (const float*)d_in[1];
    const int*   cls_idx = (const int*)  d_in[2];
    const float* U_w     = (const float*)d_in[3];
    const float* V_w     = (const float*)d_in[4];
    const float* Wc_w    = (const float*)d_in[5];
    const float* P_w     = (const float*)d_in[6];

    float* out_mask = (float*)d_out;                 // 4,096,000 elems
    float* out_O    = (float*)d_out + MASK_ELEMS;    // 4,096 elems

    // 2016 pair-warps + 64 diagonal warps = 2080 warps -> 260 blocks x 256
    relation_O_kernel<<<260, 256>>>(bbox, cls_idx, U_w, V_w, Wc_w, P_w, out_O);

    // 125 pixel chunks x 2 i-halves
    dim3 grid(125, 2);
    mask_update_kernel<<<grid, 256>>>(mask, out_mask);
}